// round 2
// baseline (speedup 1.0000x reference)
#include <cuda_runtime.h>
#include <cuda_bf16.h>
#include <math.h>

#define TT 1024
#define NENV 8192
#define CHUNKS 32
#define STEPS 32           // TT / CHUNKS
#define MTOT (TT * NENV)   // 8388608

#define GAMMA_F 0.99f
#define GL_F (0.99f * 0.95f)
#define CLIP_LO 0.8f
#define CLIP_HI 1.2f

// ---------------- scratch (device globals; no allocation allowed) ------------
__device__ float g_adv[MTOT];          // raw (unnormalized) advantages = gae
__device__ float g_A[CHUNKS * NENV];   // chunk affine coeff A
__device__ float g_B[CHUNKS * NENV];   // chunk affine coeff B
__device__ float g_gin[CHUNKS * NENV]; // incoming gae per chunk
__device__ double g_acc[5];            // 0:sum_g 1:sumsq_g 2:vloss 3:entropy 4:action_sum
__device__ float g_stats[2];           // mean, inv_std

// ---------------- helpers ----------------------------------------------------
__device__ __forceinline__ float block_reduce(float v, float* smem) {
    // blockDim.x == 256 (8 warps)
    #pragma unroll
    for (int o = 16; o > 0; o >>= 1) v += __shfl_down_sync(0xffffffffu, v, o);
    int lane = threadIdx.x & 31, w = threadIdx.x >> 5;
    if (lane == 0) smem[w] = v;
    __syncthreads();
    if (w == 0) {
        v = (lane < 8) ? smem[lane] : 0.0f;
        #pragma unroll
        for (int o = 4; o > 0; o >>= 1) v += __shfl_down_sync(0xffffffffu, v, o);
    }
    return v; // valid on thread 0
}

// ---------------- K0: zero accumulators (needed every graph replay) ----------
__global__ void k_init() {
    int i = threadIdx.x;
    if (i < 5) g_acc[i] = 0.0;
}

// ---------------- K1: per-chunk affine composition ---------------------------
__global__ void __launch_bounds__(256) k_coeff(
    const float* __restrict__ rew, const float* __restrict__ masks,
    const float* __restrict__ bad, const float* __restrict__ vp,
    const float* __restrict__ lastv)
{
    int n = blockIdx.x * blockDim.x + threadIdx.x;
    int c = blockIdx.y;
    int lo = c * STEPS, hi = lo + STEPS;

    float v_next = (hi == TT) ? lastv[n] : vp[hi * NENV + n];
    float A = 1.0f, B = 0.0f;
    #pragma unroll 8
    for (int t = hi - 1; t >= lo; --t) {
        float v  = vp[t * NENV + n];
        float m  = masks[(t + 1) * NENV + n];
        float bd = bad[(t + 1) * NENV + n];
        float r  = rew[t * NENV + n];
        float delta = r + GAMMA_F * v_next * m - v;
        float a = GL_F * m * bd;
        float b = delta * bd;
        A = a * A;
        B = a * B + b;
        v_next = v;
    }
    g_A[c * NENV + n] = A;
    g_B[c * NENV + n] = B;
}

// ---------------- K2: per-env scan over chunk coefficients -------------------
__global__ void __launch_bounds__(256) k_chunkscan() {
    int n = blockIdx.x * blockDim.x + threadIdx.x;
    float g = 0.0f; // gae at t = T is 0
    #pragma unroll
    for (int c = CHUNKS - 1; c >= 0; --c) {
        g_gin[c * NENV + n] = g;
        g = g_A[c * NENV + n] * g + g_B[c * NENV + n];
    }
}

// ---------------- K3: main pass — adv values + value loss + entropy ----------
__global__ void __launch_bounds__(256) k_main(
    const float* __restrict__ rew, const float* __restrict__ masks,
    const float* __restrict__ bad, const float* __restrict__ vp,
    const float* __restrict__ lastv, const float* __restrict__ nval,
    const float* __restrict__ ent)
{
    __shared__ float sm0[8], sm1[8], sm2[8], sm3[8];
    int n = blockIdx.x * blockDim.x + threadIdx.x;
    int c = blockIdx.y;
    int lo = c * STEPS, hi = lo + STEPS;

    float g = g_gin[c * NENV + n];
    float v_next = (hi == TT) ? lastv[n] : vp[hi * NENV + n];

    float s = 0.f, s2 = 0.f, vl = 0.f, es = 0.f;
    #pragma unroll 8
    for (int t = hi - 1; t >= lo; --t) {
        int idx = t * NENV + n;
        float v  = vp[idx];
        float m  = masks[idx + NENV];
        float bd = bad[idx + NENV];
        float r  = rew[idx];
        float nv = nval[idx];
        float en = ent[idx];

        float delta = r + GAMMA_F * v_next * m - v;
        g = (delta + GL_F * m * g) * bd;
        g_adv[idx] = g;

        s  += g;
        s2 += g * g;

        float ret = g + v;                         // returns_t
        float dc  = fminf(fmaxf(nv - v, -0.2f), 0.2f);
        float vpc = v + dc;                        // value_pred_clipped
        float d1 = nv - ret, d2 = vpc - ret;
        vl += fmaxf(d1 * d1, d2 * d2);
        es += en;

        v_next = v;
    }

    float rs  = block_reduce(s,  sm0);
    float rs2 = block_reduce(s2, sm1);
    float rvl = block_reduce(vl, sm2);
    float res = block_reduce(es, sm3);
    if (threadIdx.x == 0) {
        atomicAdd(&g_acc[0], (double)rs);
        atomicAdd(&g_acc[1], (double)rs2);
        atomicAdd(&g_acc[2], (double)rvl);
        atomicAdd(&g_acc[3], (double)res);
    }
}

// ---------------- K4: finalize normalization stats ---------------------------
__global__ void k_stats() {
    double S = g_acc[0], S2 = g_acc[1];
    double M = (double)MTOT;
    double mean = S / M;
    double var = (S2 - S * S / M) / (M - 1.0);
    double sd = sqrt(var);
    g_stats[0] = (float)mean;
    g_stats[1] = (float)(1.0 / (sd + 1e-5));
}

// ---------------- K5: action loss (vectorized) -------------------------------
__global__ void __launch_bounds__(256) k_action(
    const float* __restrict__ lp, const float* __restrict__ plp)
{
    __shared__ float sm[8];
    int i = blockIdx.x * blockDim.x + threadIdx.x; // float4 index
    const float4* a4 = reinterpret_cast<const float4*>(g_adv);
    const float4* l4 = reinterpret_cast<const float4*>(lp);
    const float4* p4 = reinterpret_cast<const float4*>(plp);
    float mean = g_stats[0], istd = g_stats[1];

    float s = 0.0f;
    float4 gv = a4[i], lv = l4[i], pv = p4[i];
    {
        float a = (gv.x - mean) * istd;
        float r = __expf(lv.x - pv.x);
        float rc = fminf(fmaxf(r, CLIP_LO), CLIP_HI);
        s += fminf(r * a, rc * a);
    }
    {
        float a = (gv.y - mean) * istd;
        float r = __expf(lv.y - pv.y);
        float rc = fminf(fmaxf(r, CLIP_LO), CLIP_HI);
        s += fminf(r * a, rc * a);
    }
    {
        float a = (gv.z - mean) * istd;
        float r = __expf(lv.z - pv.z);
        float rc = fminf(fmaxf(r, CLIP_LO), CLIP_HI);
        s += fminf(r * a, rc * a);
    }
    {
        float a = (gv.w - mean) * istd;
        float r = __expf(lv.w - pv.w);
        float rc = fminf(fmaxf(r, CLIP_LO), CLIP_HI);
        s += fminf(r * a, rc * a);
    }

    float rsum = block_reduce(s, sm);
    if (threadIdx.x == 0) atomicAdd(&g_acc[4], (double)rsum);
}

// ---------------- K6: combine scalar loss ------------------------------------
__global__ void k_final(float* __restrict__ out) {
    double M = (double)MTOT;
    double value_loss = 0.5 * (g_acc[2] / M);   // 0.5 * mean(max(...))
    double action_loss = -(g_acc[4] / M);
    double ent_mean = g_acc[3] / M;
    double loss = value_loss * 0.5 + action_loss - 0.01 * ent_mean;
    out[0] = (float)loss;
}

// ---------------- launch ------------------------------------------------------
extern "C" void kernel_launch(void* const* d_in, const int* in_sizes, int n_in,
                              void* d_out, int out_size)
{
    const float* rew   = (const float*)d_in[0];
    const float* masks = (const float*)d_in[1];
    const float* bad   = (const float*)d_in[2];
    const float* vp    = (const float*)d_in[3];
    const float* lastv = (const float*)d_in[4];
    const float* lp    = (const float*)d_in[5];
    const float* plp   = (const float*)d_in[6];
    const float* nval  = (const float*)d_in[7];
    const float* ent   = (const float*)d_in[8];
    float* out = (float*)d_out;

    k_init<<<1, 32>>>();

    dim3 grid2(NENV / 256, CHUNKS);
    k_coeff<<<grid2, 256>>>(rew, masks, bad, vp, lastv);
    k_chunkscan<<<NENV / 256, 256>>>();
    k_main<<<grid2, 256>>>(rew, masks, bad, vp, lastv, nval, ent);
    k_stats<<<1, 1>>>();
    k_action<<<(MTOT / 4) / 256, 256>>>(lp, plp);
    k_final<<<1, 1>>>(out);
}